// round 15
// baseline (speedup 1.0000x reference)
#include <cuda_runtime.h>
#include <cuda_bf16.h>
#include <cuda_fp16.h>
#include <cstdint>

#define Bn 8
#define SQn 2048
#define SKn 2048
#define Dh 512
#define THREADS 256
// qk tiles: k=32 chunks, pitch 80B
#define PITCHB 80
#define TBk (128 * PITCHB)          // 10240
#define QB2 (2 * TBk)               // 20480 (H+L pair)
#define TILES_OFF 1024
#define SMEM_QK (TILES_OFF + 5 * QB2)        // 103424
// pv tiles: k=64 chunks, pitch 144B
#define PITCHB2 144
#define TB64 (128 * PITCHB2)        // 18432
#define PVSTAGE (2 * TB64)          // 36864 (P+V pair)
#define SMEM_PV (TILES_OFF + 3 * PVSTAGE)    // 111616

__device__ __nv_bfloat16 g_Qh[Bn * SQn * Dh], g_Ql[Bn * SQn * Dh];
__device__ __nv_bfloat16 g_Kh[Bn * SKn * Dh], g_Kl[Bn * SKn * Dh];
__device__ __half g_Vf[(size_t)Bn * SKn * Dh];     // fp16 transposed [b][d][sk]
__device__ float g_S[(size_t)Bn * SQn * SKn];
__device__ __half g_Pf[(size_t)Bn * SQn * SKn];
__device__ unsigned g_rmk[Bn * SQn];
__device__ float g_rsum[Bn * SQn];

// ---------------- helpers ----------------
__device__ __forceinline__ uint32_t smem_to_u32(const void* p) {
    uint32_t a;
    asm("{ .reg .u64 t; cvta.to.shared.u64 t, %1; cvt.u32.u64 %0, t; }" : "=r"(a) : "l"(p));
    return a;
}
__device__ __forceinline__ void ldsm4(uint32_t* r, uint32_t addr) {
    asm volatile("ldmatrix.sync.aligned.m8n8.x4.shared.b16 {%0,%1,%2,%3}, [%4];"
        : "=r"(r[0]), "=r"(r[1]), "=r"(r[2]), "=r"(r[3]) : "r"(addr));
}
__device__ __forceinline__ void mma16816(float* c, const uint32_t* a, const uint32_t* b) {
    asm volatile("mma.sync.aligned.m16n8k16.row.col.f32.bf16.bf16.f32 "
        "{%0,%1,%2,%3}, {%4,%5,%6,%7}, {%8,%9}, {%0,%1,%2,%3};"
        : "+f"(c[0]), "+f"(c[1]), "+f"(c[2]), "+f"(c[3])
        : "r"(a[0]), "r"(a[1]), "r"(a[2]), "r"(a[3]), "r"(b[0]), "r"(b[1]));
}
__device__ __forceinline__ void mma16816h(float* c, const uint32_t* a, const uint32_t* b) {
    asm volatile("mma.sync.aligned.m16n8k16.row.col.f32.f16.f16.f32 "
        "{%0,%1,%2,%3}, {%4,%5,%6,%7}, {%8,%9}, {%0,%1,%2,%3};"
        : "+f"(c[0]), "+f"(c[1]), "+f"(c[2]), "+f"(c[3])
        : "r"(a[0]), "r"(a[1]), "r"(a[2]), "r"(a[3]), "r"(b[0]), "r"(b[1]));
}
__device__ __forceinline__ void cpasync16(uint32_t dst, const void* src) {
    asm volatile("cp.async.cg.shared.global [%0], [%1], 16;" :: "r"(dst), "l"(src));
}
#define CP_COMMIT() asm volatile("cp.async.commit_group;" ::: "memory")
#define CP_WAIT1()  asm volatile("cp.async.wait_group 1;" ::: "memory")
__device__ __forceinline__ unsigned short uh(__half h) { return __half_as_ushort(h); }
__device__ __forceinline__ unsigned fkey(float x) {
    unsigned u = __float_as_uint(x);
    return (u & 0x80000000u) ? ~u : (u | 0x80000000u);
}
__device__ __forceinline__ float fdec(unsigned k) {
    return (k & 0x80000000u) ? __uint_as_float(k ^ 0x80000000u) : __uint_as_float(~k);
}

// ---------------- prep ----------------
__global__ void prep_all(const float* __restrict__ q, const float* __restrict__ k,
                         const float* __restrict__ v) {
    __shared__ float t[32][33];
    const int b = blockIdx.z;
    const int sk0 = blockIdx.x * 32, d0 = blockIdx.y * 32;
    const int tx = threadIdx.x & 31, ty = threadIdx.x >> 5;
    #pragma unroll
    for (int rr = 0; rr < 32; rr += 8)
        t[ty + rr][tx] = v[(((size_t)b * SKn + sk0 + ty + rr) << 9) + d0 + tx];
    __syncthreads();
    #pragma unroll
    for (int rr = 0; rr < 32; rr += 8) {
        int d = d0 + ty + rr;
        g_Vf[((size_t)b * Dh + d) * SKn + sk0 + tx] = __float2half(t[tx][ty + rr]);
    }
    const int n = Bn * SQn * Dh;
    const int gid = (blockIdx.z * gridDim.y * gridDim.x + blockIdx.y * gridDim.x + blockIdx.x)
                    * blockDim.x + threadIdx.x;
    const int stride = gridDim.x * gridDim.y * gridDim.z * blockDim.x;
    if (gid < Bn * SQn) g_rmk[gid] = 0u;
    for (int i = gid; i < n; i += stride) {
        float x = q[i];
        __nv_bfloat16 h = __float2bfloat16(x);
        g_Qh[i] = h;
        g_Ql[i] = __float2bfloat16(x - __bfloat162float(h));
        float y = k[i];
        __nv_bfloat16 g = __float2bfloat16(y);
        g_Kh[i] = g;
        g_Kl[i] = __float2bfloat16(y - __bfloat162float(g));
    }
}

// ---------------- kernel 1: S = Q K^T (bf16x3), warp 32x64, 256 thr ----------------
__global__ void __launch_bounds__(THREADS, 2)
qk_kern() {
    extern __shared__ char smem[];
    const uint32_t sTiles = smem_to_u32(smem) + TILES_OFF;

    const int tid = threadIdx.x, wid = tid >> 5, lane = tid & 31;
    const int wq = wid >> 1, nh = wid & 1;          // 4 q-groups x 2 n-groups
    const int skq = blockIdx.x, qt = blockIdx.y, b = blockIdx.z;

    const __nv_bfloat16* Qh = g_Qh + ((size_t)b * SQn + qt * 128) * Dh;
    const __nv_bfloat16* Ql = g_Ql + ((size_t)b * SQn + qt * 128) * Dh;
    const __nv_bfloat16* Kh = g_Kh + (size_t)b * SKn * Dh;
    const __nv_bfloat16* Kl = g_Kl + (size_t)b * SKn * Dh;
    float* strip = g_S + ((size_t)(b * 16 + qt)) * ((size_t)128 * SKn);
    unsigned* rmk = g_rmk + b * SQn + qt * 128;

    // warp tile: 32 q-rows (2 m16) x 64 n-cols (4 n16)
    const uint32_t aoff = (uint32_t)((wq * 32 + (lane & 7) + ((lane >> 3) & 1) * 8) * PITCHB
                                     + (lane >> 4) * 16);
    const uint32_t boff = (uint32_t)((nh * 64 + (lane & 7) + (lane >> 4) * 8) * PITCHB
                                     + ((lane >> 3) & 1) * 16);
    const int fr0 = tid >> 1, fcb = (tid & 1) * 2;   // 2 chunks/thread/tile

    const uint32_t kBase = sTiles + 2 * QB2;

    #define LOAD_Q(i) do { \
        int dcq = (i) & 15; \
        uint32_t d = sTiles + ((i) & 1) * QB2 + (uint32_t)(fr0 * PITCHB + fcb * 16); \
        size_t qo = (size_t)fr0 * Dh + dcq * 32 + fcb * 8; \
        cpasync16(d, Qh + qo);       cpasync16(d + 16, Qh + qo + 8); \
        cpasync16(d + TBk, Ql + qo); cpasync16(d + TBk + 16, Ql + qo + 8); \
    } while (0)
    #define LOAD_K(i) do { \
        int ktg = skq * 4 + ((i) >> 4), dck = (i) & 15; \
        uint32_t d = kBase + ((i) % 3) * QB2 + (uint32_t)(fr0 * PITCHB + fcb * 16); \
        size_t ko = (size_t)(ktg * 128 + fr0) * Dh + dck * 32 + fcb * 8; \
        cpasync16(d, Kh + ko);       cpasync16(d + 16, Kh + ko + 8); \
        cpasync16(d + TBk, Kl + ko); cpasync16(d + TBk + 16, Kl + ko + 8); \
    } while (0)

    float acc[16][4];   // [m*8 + nf*2 + n8]

    LOAD_K(0); CP_COMMIT();
    LOAD_Q(0); CP_COMMIT();
    LOAD_K(1); CP_COMMIT();

    for (int step = 0; step < 64; step++) {
        const int dc1 = step & 15;
        if (dc1 == 0) {
            #pragma unroll
            for (int f = 0; f < 16; f++)
                #pragma unroll
                for (int j = 0; j < 4; j++) acc[f][j] = 0.0f;
        }
        CP_WAIT1();
        __syncthreads();
        if (step + 1 < 64) LOAD_Q(step + 1);
        CP_COMMIT();
        if (step + 2 < 64) LOAD_K(step + 2);
        CP_COMMIT();

        const uint32_t sAH = sTiles + (step & 1) * QB2;
        const uint32_t sAL = sAH + TBk;
        const uint32_t sBH = kBase + (step % 3) * QB2;
        const uint32_t sBL = sBH + TBk;
        #pragma unroll
        for (int ks = 0; ks < 2; ks++) {
            uint32_t ah[2][4], al[2][4];
            ldsm4(ah[0], sAH + aoff + ks * 32);
            ldsm4(ah[1], sAH + aoff + 16 * PITCHB + ks * 32);
            ldsm4(al[0], sAL + aoff + ks * 32);
            ldsm4(al[1], sAL + aoff + 16 * PITCHB + ks * 32);
            #pragma unroll
            for (int nf = 0; nf < 4; nf++) {
                uint32_t bh[4], bl[4];
                uint32_t bo = boff + (uint32_t)(nf * (16 * PITCHB) + ks * 32);
                ldsm4(bh, sBH + bo);
                ldsm4(bl, sBL + bo);
                #pragma unroll
                for (int m = 0; m < 2; m++)
                    #pragma unroll
                    for (int n8 = 0; n8 < 2; n8++) {
                        float* c = acc[m * 8 + nf * 2 + n8];
                        mma16816(c, ah[m], bh + n8 * 2);
                        mma16816(c, ah[m], bl + n8 * 2);
                        mma16816(c, al[m], bh + n8 * 2);
                    }
            }
        }
        if (dc1 == 15) {   // spill S tile + atomic rowmax
            const int ktg = skq * 4 + (step >> 4);
            #pragma unroll
            for (int m = 0; m < 2; m++) {
                int row = wq * 32 + m * 16 + (lane >> 2);
                float m0 = -1e30f, m1 = -1e30f;
                #pragma unroll
                for (int f8 = 0; f8 < 8; f8++) {
                    float* c = acc[m * 8 + f8];
                    int col = nh * 64 + f8 * 8 + (lane & 3) * 2;
                    float* s0 = strip + (size_t)ktg * 16384 + row * 128 + col;
                    m0 = fmaxf(m0, fmaxf(c[0], c[1]));
                    m1 = fmaxf(m1, fmaxf(c[2], c[3]));
                    *(float2*)s0 = make_float2(c[0], c[1]);
                    *(float2*)(s0 + 8 * 128) = make_float2(c[2], c[3]);
                }
                m0 = fmaxf(m0, __shfl_xor_sync(0xffffffffu, m0, 1));
                m0 = fmaxf(m0, __shfl_xor_sync(0xffffffffu, m0, 2));
                m1 = fmaxf(m1, __shfl_xor_sync(0xffffffffu, m1, 1));
                m1 = fmaxf(m1, __shfl_xor_sync(0xffffffffu, m1, 2));
                if ((lane & 3) == 0) {
                    atomicMax(&rmk[row], fkey(m0));
                    atomicMax(&rmk[row + 8], fkey(m1));
                }
            }
        }
    }
    #undef LOAD_Q
    #undef LOAD_K
}

// ---------------- kernel 2: softmax -> fp16 P + rowsum ----------------
__global__ void __launch_bounds__(256, 4)
sm_kern() {
    const int wid = threadIdx.x >> 5, lane = threadIdx.x & 31;
    #pragma unroll
    for (int i = 0; i < 8; i++) {
        int g = blockIdx.x * 64 + wid * 8 + i;
        int b = g >> 11, rq = g & 2047;
        int qt = rq >> 7, rr = rq & 127;
        const float* strip = g_S + ((size_t)(b * 16 + qt)) * ((size_t)128 * SKn);
        __half* Pf = g_Pf + ((size_t)b * SQn + rq) * SKn;
        float m = fdec(g_rmk[g]);
        float s = 0.0f;
        for (int kt = 0; kt < 16; kt++) {
            float4 vv = *(const float4*)(strip + (size_t)kt * 16384 + rr * 128 + lane * 4);
            float p0 = __expf(vv.x - m), p1 = __expf(vv.y - m);
            float p2 = __expf(vv.z - m), p3 = __expf(vv.w - m);
            s += (p0 + p1) + (p2 + p3);
            uint2 hw;
            hw.x = (uint32_t)uh(__float2half(p0)) | ((uint32_t)uh(__float2half(p1)) << 16);
            hw.y = (uint32_t)uh(__float2half(p2)) | ((uint32_t)uh(__float2half(p3)) << 16);
            *(uint2*)(Pf + kt * 128 + lane * 4) = hw;
        }
        #pragma unroll
        for (int off = 16; off; off >>= 1) s += __shfl_xor_sync(0xffffffffu, s, off);
        if (lane == 0) g_rsum[g] = s;
    }
}

// ---------------- kernel 3: O = P V (fp16), warp 32x64, k=64, 3-stage ----------------
__global__ void __launch_bounds__(THREADS, 2)
pv_kern(float* __restrict__ out) {
    extern __shared__ char smem[];
    const uint32_t sTiles = smem_to_u32(smem) + TILES_OFF;

    const int tid = threadIdx.x, wid = tid >> 5, lane = tid & 31;
    const int wq = wid >> 1, nh = wid & 1;
    const int dc = blockIdx.x, qt = blockIdx.y, b = blockIdx.z;

    const __half* Pf = g_Pf + ((size_t)b * SQn + qt * 128) * SKn;
    const __half* Vf = g_Vf + ((size_t)b * Dh + dc * 128) * SKn;
    const float* rsum = g_rsum + b * SQn + qt * 128;

    const uint32_t aoff = (uint32_t)((wq * 32 + (lane & 7) + ((lane >> 3) & 1) * 8) * PITCHB2
                                     + (lane >> 4) * 16);
    const uint32_t boff = (uint32_t)((nh * 64 + (lane & 7) + (lane >> 4) * 8) * PITCHB2
                                     + ((lane >> 3) & 1) * 16);
    const int fr0 = tid >> 1, fcb = (tid & 1) * 4;   // 4 chunks/thread/tile

    #define LOAD_PV(i) do { \
        uint32_t base = sTiles + ((i) % 3) * PVSTAGE; \
        _Pragma("unroll") \
        for (int j = 0; j < 4; j++) { \
            int c = fcb + j; \
            uint32_t d = base + (uint32_t)(fr0 * PITCHB2 + c * 16); \
            cpasync16(d, Pf + (size_t)fr0 * SKn + (i) * 64 + c * 8); \
            cpasync16(d + TB64, Vf + (size_t)fr0 * SKn + (i) * 64 + c * 8); \
        } \
    } while (0)

    float acc[16][4];
    #pragma unroll
    for (int f = 0; f < 16; f++)
        #pragma unroll
        for (int j = 0; j < 4; j++) acc[f][j] = 0.0f;

    LOAD_PV(0); CP_COMMIT();
    LOAD_PV(1); CP_COMMIT();

    for (int step = 0; step < 32; step++) {
        CP_WAIT1();
        __syncthreads();
        if (step + 2 < 32) LOAD_PV(step + 2);
        CP_COMMIT();

        const uint32_t sA = sTiles + (step % 3) * PVSTAGE;
        const uint32_t sB = sA + TB64;
        #pragma unroll
        for (int ks = 0; ks < 4; ks++) {
            uint32_t a4[2][4];
            ldsm4(a4[0], sA + aoff + ks * 32);
            ldsm4(a4[1], sA + aoff + 16 * PITCHB2 + ks * 32);
            #pragma unroll
            for (int nf = 0; nf < 4; nf++) {
                uint32_t b4[4];
                ldsm4(b4, sB + boff + (uint32_t)(nf * (16 * PITCHB2) + ks * 32));
                #pragma unroll
                for (int m = 0; m < 2; m++)
                    #pragma unroll
                    for (int n8 = 0; n8 < 2; n8++)
                        mma16816h(acc[m * 8 + nf * 2 + n8], a4[m], b4 + n8 * 2);
            }
        }
    }
    #undef LOAD_PV
    // epilogue
    #pragma unroll
    for (int m = 0; m < 2; m++) {
        int row = wq * 32 + m * 16 + (lane >> 2);
        float inv0 = 1.0f / rsum[row];
        float inv1 = 1.0f / rsum[row + 8];
        #pragma unroll
        for (int f8 = 0; f8 < 8; f8++) {
            float* c = acc[m * 8 + f8];
            int col = dc * 128 + nh * 64 + f8 * 8 + (lane & 3) * 2;
            float* o0 = out + ((size_t)b * SQn + qt * 128 + row) * Dh + col;
            *(float2*)o0 = make_float2(c[0] * inv0, c[1] * inv0);
            *(float2*)(o0 + 8 * Dh) = make_float2(c[2] * inv1, c[3] * inv1);
        }
    }
}

extern "C" void kernel_launch(void* const* d_in, const int* in_sizes, int n_in,
                              void* d_out, int out_size) {
    (void)in_sizes; (void)n_in; (void)out_size;
    const float* q = (const float*)d_in[0];
    const float* k = (const float*)d_in[1];
    const float* v = (const float*)d_in[2];
    float* out = (float*)d_out;

    cudaFuncSetAttribute(qk_kern, cudaFuncAttributeMaxDynamicSharedMemorySize, SMEM_QK);
    cudaFuncSetAttribute(pv_kern, cudaFuncAttributeMaxDynamicSharedMemorySize, SMEM_PV);

    dim3 pgrid(SKn / 32, Dh / 32, Bn);
    prep_all<<<pgrid, 256>>>(q, k, v);
    dim3 g1(4, 16, Bn);
    qk_kern<<<g1, THREADS, SMEM_QK>>>();
    sm_kern<<<256, 256>>>();
    dim3 g3(4, 16, Bn);
    pv_kern<<<g3, THREADS, SMEM_PV>>>(out);
}

// round 16
// speedup vs baseline: 1.2541x; 1.2541x over previous
#include <cuda_runtime.h>
#include <cuda_bf16.h>
#include <cuda_fp16.h>
#include <cstdint>

#define Bn 8
#define SQn 2048
#define SKn 2048
#define Dh 512
#define THREADS 512
// qk tiles: k=32 chunks, pitch 80B
#define PITCHB 80
#define TBk (128 * PITCHB)          // 10240
#define QB2 (2 * TBk)               // 20480 (H+L pair)
#define TILES_OFF 1024
#define SMEM_QK (TILES_OFF + 5 * QB2)        // 103424
// pv tiles: k=64 chunks, pitch 144B
#define PITCHB2 144
#define TB64 (128 * PITCHB2)        // 18432
#define PVSTAGE (2 * TB64)          // 36864 (P+V pair)
#define SMEM_PV (TILES_OFF + 3 * PVSTAGE)    // 111616

__device__ __nv_bfloat16 g_Qh[Bn * SQn * Dh], g_Ql[Bn * SQn * Dh];
__device__ __nv_bfloat16 g_Kh[Bn * SKn * Dh], g_Kl[Bn * SKn * Dh];
__device__ __half g_Vf[(size_t)Bn * SKn * Dh];     // fp16 transposed [b][d][sk]
__device__ float g_S[(size_t)Bn * SQn * SKn];
__device__ __half g_Pf[(size_t)Bn * SQn * SKn];
__device__ unsigned g_rmk[Bn * SQn];
__device__ float g_rsum[Bn * SQn];

// ---------------- helpers ----------------
__device__ __forceinline__ uint32_t smem_to_u32(const void* p) {
    uint32_t a;
    asm("{ .reg .u64 t; cvta.to.shared.u64 t, %1; cvt.u32.u64 %0, t; }" : "=r"(a) : "l"(p));
    return a;
}
__device__ __forceinline__ void ldsm4(uint32_t* r, uint32_t addr) {
    asm volatile("ldmatrix.sync.aligned.m8n8.x4.shared.b16 {%0,%1,%2,%3}, [%4];"
        : "=r"(r[0]), "=r"(r[1]), "=r"(r[2]), "=r"(r[3]) : "r"(addr));
}
__device__ __forceinline__ void mma16816(float* c, const uint32_t* a, const uint32_t* b) {
    asm volatile("mma.sync.aligned.m16n8k16.row.col.f32.bf16.bf16.f32 "
        "{%0,%1,%2,%3}, {%4,%5,%6,%7}, {%8,%9}, {%0,%1,%2,%3};"
        : "+f"(c[0]), "+f"(c[1]), "+f"(c[2]), "+f"(c[3])
        : "r"(a[0]), "r"(a[1]), "r"(a[2]), "r"(a[3]), "r"(b[0]), "r"(b[1]));
}
__device__ __forceinline__ void mma16816h(float* c, const uint32_t* a, const uint32_t* b) {
    asm volatile("mma.sync.aligned.m16n8k16.row.col.f32.f16.f16.f32 "
        "{%0,%1,%2,%3}, {%4,%5,%6,%7}, {%8,%9}, {%0,%1,%2,%3};"
        : "+f"(c[0]), "+f"(c[1]), "+f"(c[2]), "+f"(c[3])
        : "r"(a[0]), "r"(a[1]), "r"(a[2]), "r"(a[3]), "r"(b[0]), "r"(b[1]));
}
__device__ __forceinline__ void cpasync16(uint32_t dst, const void* src) {
    asm volatile("cp.async.cg.shared.global [%0], [%1], 16;" :: "r"(dst), "l"(src));
}
#define CP_COMMIT() asm volatile("cp.async.commit_group;" ::: "memory")
#define CP_WAIT1()  asm volatile("cp.async.wait_group 1;" ::: "memory")
__device__ __forceinline__ unsigned short uh(__half h) { return __half_as_ushort(h); }
__device__ __forceinline__ unsigned fkey(float x) {
    unsigned u = __float_as_uint(x);
    return (u & 0x80000000u) ? ~u : (u | 0x80000000u);
}
__device__ __forceinline__ float fdec(unsigned k) {
    return (k & 0x80000000u) ? __uint_as_float(k ^ 0x80000000u) : __uint_as_float(~k);
}

// ---------------- prep ----------------
__global__ void prep_all(const float* __restrict__ q, const float* __restrict__ k,
                         const float* __restrict__ v) {
    __shared__ float t[32][33];
    const int b = blockIdx.z;
    const int sk0 = blockIdx.x * 32, d0 = blockIdx.y * 32;
    const int tx = threadIdx.x & 31, ty = threadIdx.x >> 5;
    #pragma unroll
    for (int rr = 0; rr < 32; rr += 8)
        t[ty + rr][tx] = v[(((size_t)b * SKn + sk0 + ty + rr) << 9) + d0 + tx];
    __syncthreads();
    #pragma unroll
    for (int rr = 0; rr < 32; rr += 8) {
        int d = d0 + ty + rr;
        g_Vf[((size_t)b * Dh + d) * SKn + sk0 + tx] = __float2half(t[tx][ty + rr]);
    }
    const int n = Bn * SQn * Dh;
    const int gid = (blockIdx.z * gridDim.y * gridDim.x + blockIdx.y * gridDim.x + blockIdx.x)
                    * blockDim.x + threadIdx.x;
    const int stride = gridDim.x * gridDim.y * gridDim.z * blockDim.x;
    if (gid < Bn * SQn) g_rmk[gid] = 0u;
    for (int i = gid; i < n; i += stride) {
        float x = q[i];
        __nv_bfloat16 h = __float2bfloat16(x);
        g_Qh[i] = h;
        g_Ql[i] = __float2bfloat16(x - __bfloat162float(h));
        float y = k[i];
        __nv_bfloat16 g = __float2bfloat16(y);
        g_Kh[i] = g;
        g_Kl[i] = __float2bfloat16(y - __bfloat162float(g));
    }
}

// ---------------- kernel 1: S = Q K^T, one K-tile per CTA (16 steps) ----------------
// grid (16 kt, 16 qt, 8 b) = 2048 CTAs; 512 thr; 4x4 warp grid; Q 2-buf / K 3-buf
__global__ void __launch_bounds__(THREADS, 2)
qk_kern() {
    extern __shared__ char smem[];
    const uint32_t sTiles = smem_to_u32(smem) + TILES_OFF;

    const int tid = threadIdx.x, wid = tid >> 5, lane = tid & 31;
    const int wq = wid >> 2, nh = wid & 3;          // 4 x 4
    const int ktg = blockIdx.x, qt = blockIdx.y, b = blockIdx.z;

    const __nv_bfloat16* Qh = g_Qh + ((size_t)b * SQn + qt * 128) * Dh;
    const __nv_bfloat16* Ql = g_Ql + ((size_t)b * SQn + qt * 128) * Dh;
    const __nv_bfloat16* Kh = g_Kh + (size_t)b * SKn * Dh;
    const __nv_bfloat16* Kl = g_Kl + (size_t)b * SKn * Dh;
    float* strip = g_S + ((size_t)(b * 16 + qt)) * ((size_t)128 * SKn);
    unsigned* rmk = g_rmk + b * SQn + qt * 128;

    const uint32_t aoff = (uint32_t)((wq * 32 + (lane & 7) + ((lane >> 3) & 1) * 8) * PITCHB
                                     + (lane >> 4) * 16);
    const uint32_t boff = (uint32_t)((nh * 32 + (lane & 7) + (lane >> 4) * 8) * PITCHB
                                     + ((lane >> 3) & 1) * 16);
    const int fr0 = tid >> 2, fc0 = tid & 3;

    const uint32_t kBase = sTiles + 2 * QB2;

    #define LOAD_Q(i) do { \
        uint32_t d = sTiles + ((i) & 1) * QB2 + (uint32_t)(fr0 * PITCHB + fc0 * 16); \
        size_t qo = (size_t)fr0 * Dh + (i) * 32 + fc0 * 8; \
        cpasync16(d, Qh + qo); \
        cpasync16(d + TBk, Ql + qo); \
    } while (0)
    #define LOAD_K(i) do { \
        uint32_t d = kBase + ((i) % 3) * QB2 + (uint32_t)(fr0 * PITCHB + fc0 * 16); \
        size_t ko = (size_t)(ktg * 128 + fr0) * Dh + (i) * 32 + fc0 * 8; \
        cpasync16(d, Kh + ko); \
        cpasync16(d + TBk, Kl + ko); \
    } while (0)

    float acc[8][4];
    #pragma unroll
    for (int f = 0; f < 8; f++)
        #pragma unroll
        for (int j = 0; j < 4; j++) acc[f][j] = 0.0f;

    LOAD_K(0); CP_COMMIT();
    LOAD_Q(0); CP_COMMIT();
    LOAD_K(1); CP_COMMIT();

    for (int step = 0; step < 16; step++) {
        CP_WAIT1();
        __syncthreads();
        if (step + 1 < 16) LOAD_Q(step + 1);
        CP_COMMIT();
        if (step + 2 < 16) LOAD_K(step + 2);
        CP_COMMIT();

        const uint32_t sAH = sTiles + (step & 1) * QB2;
        const uint32_t sAL = sAH + TBk;
        const uint32_t sBH = kBase + (step % 3) * QB2;
        const uint32_t sBL = sBH + TBk;
        #pragma unroll
        for (int ks = 0; ks < 2; ks++) {
            uint32_t ah[2][4], al[2][4];
            ldsm4(ah[0], sAH + aoff + ks * 32);
            ldsm4(ah[1], sAH + aoff + 16 * PITCHB + ks * 32);
            ldsm4(al[0], sAL + aoff + ks * 32);
            ldsm4(al[1], sAL + aoff + 16 * PITCHB + ks * 32);
            #pragma unroll
            for (int nf = 0; nf < 2; nf++) {
                uint32_t bh[4], bl[4];
                uint32_t bo = boff + (uint32_t)(nf * (16 * PITCHB) + ks * 32);
                ldsm4(bh, sBH + bo);
                ldsm4(bl, sBL + bo);
                #pragma unroll
                for (int m = 0; m < 2; m++)
                    #pragma unroll
                    for (int n8 = 0; n8 < 2; n8++) {
                        float* c = acc[m * 4 + nf * 2 + n8];
                        mma16816(c, ah[m], bh + n8 * 2);
                        mma16816(c, ah[m], bl + n8 * 2);
                        mma16816(c, al[m], bh + n8 * 2);
                    }
            }
        }
    }
    // spill S tile + atomic rowmax
    #pragma unroll
    for (int m = 0; m < 2; m++) {
        int row = wq * 32 + m * 16 + (lane >> 2);
        float m0 = -1e30f, m1 = -1e30f;
        #pragma unroll
        for (int f4 = 0; f4 < 4; f4++) {
            float* c = acc[m * 4 + f4];
            int col = nh * 32 + f4 * 8 + (lane & 3) * 2;
            float* s0 = strip + (size_t)ktg * 16384 + row * 128 + col;
            m0 = fmaxf(m0, fmaxf(c[0], c[1]));
            m1 = fmaxf(m1, fmaxf(c[2], c[3]));
            *(float2*)s0 = make_float2(c[0], c[1]);
            *(float2*)(s0 + 8 * 128) = make_float2(c[2], c[3]);
        }
        m0 = fmaxf(m0, __shfl_xor_sync(0xffffffffu, m0, 1));
        m0 = fmaxf(m0, __shfl_xor_sync(0xffffffffu, m0, 2));
        m1 = fmaxf(m1, __shfl_xor_sync(0xffffffffu, m1, 1));
        m1 = fmaxf(m1, __shfl_xor_sync(0xffffffffu, m1, 2));
        if ((lane & 3) == 0) {
            atomicMax(&rmk[row], fkey(m0));
            atomicMax(&rmk[row + 8], fkey(m1));
        }
    }
    #undef LOAD_Q
    #undef LOAD_K
}

// ---------------- kernel 2: softmax -> fp16 P + rowsum ----------------
__global__ void __launch_bounds__(256, 4)
sm_kern() {
    const int wid = threadIdx.x >> 5, lane = threadIdx.x & 31;
    #pragma unroll
    for (int i = 0; i < 8; i++) {
        int g = blockIdx.x * 64 + wid * 8 + i;
        int b = g >> 11, rq = g & 2047;
        int qt = rq >> 7, rr = rq & 127;
        const float* strip = g_S + ((size_t)(b * 16 + qt)) * ((size_t)128 * SKn);
        __half* Pf = g_Pf + ((size_t)b * SQn + rq) * SKn;
        float m = fdec(g_rmk[g]);
        float s = 0.0f;
        for (int kt = 0; kt < 16; kt++) {
            float4 vv = *(const float4*)(strip + (size_t)kt * 16384 + rr * 128 + lane * 4);
            float p0 = __expf(vv.x - m), p1 = __expf(vv.y - m);
            float p2 = __expf(vv.z - m), p3 = __expf(vv.w - m);
            s += (p0 + p1) + (p2 + p3);
            uint2 hw;
            hw.x = (uint32_t)uh(__float2half(p0)) | ((uint32_t)uh(__float2half(p1)) << 16);
            hw.y = (uint32_t)uh(__float2half(p2)) | ((uint32_t)uh(__float2half(p3)) << 16);
            *(uint2*)(Pf + kt * 128 + lane * 4) = hw;
        }
        #pragma unroll
        for (int off = 16; off; off >>= 1) s += __shfl_xor_sync(0xffffffffu, s, off);
        if (lane == 0) g_rsum[g] = s;
    }
}

// ---------------- kernel 3: O = P V (fp16), k=64, 3-stage pipelined ----------------
__global__ void __launch_bounds__(THREADS, 2)
pv_kern(float* __restrict__ out) {
    extern __shared__ char smem[];
    const uint32_t sTiles = smem_to_u32(smem) + TILES_OFF;

    const int tid = threadIdx.x, wid = tid >> 5, lane = tid & 31;
    const int wq = wid >> 2, nh = wid & 3;
    const int dc = blockIdx.x, qt = blockIdx.y, b = blockIdx.z;

    const __half* Pf = g_Pf + ((size_t)b * SQn + qt * 128) * SKn;
    const __half* Vf = g_Vf + ((size_t)b * Dh + dc * 128) * SKn;
    const float* rsum = g_rsum + b * SQn + qt * 128;

    const uint32_t aoff = (uint32_t)((wq * 32 + (lane & 7) + ((lane >> 3) & 1) * 8) * PITCHB2
                                     + (lane >> 4) * 16);
    const uint32_t boff = (uint32_t)((nh * 32 + (lane & 7) + (lane >> 4) * 8) * PITCHB2
                                     + ((lane >> 3) & 1) * 16);
    const int fr0 = tid >> 2, fc0 = (tid & 3) << 1;

    #define LOAD_PV(i) do { \
        uint32_t base = sTiles + ((i) % 3) * PVSTAGE; \
        _Pragma("unroll") \
        for (int j = 0; j < 2; j++) { \
            int c = fc0 + j; \
            uint32_t d = base + (uint32_t)(fr0 * PITCHB2 + c * 16); \
            cpasync16(d, Pf + (size_t)fr0 * SKn + (i) * 64 + c * 8); \
            cpasync16(d + TB64, Vf + (size_t)fr0 * SKn + (i) * 64 + c * 8); \
        } \
    } while (0)

    float acc[8][4];
    #pragma unroll
    for (int f = 0; f < 8; f++)
        #pragma unroll
        for (int j = 0; j < 4; j++) acc[f][j] = 0.0f;

    LOAD_PV(0); CP_COMMIT();
    LOAD_PV(1); CP_COMMIT();

    for (int step = 0; step < 32; step++) {
        CP_WAIT1();
        __syncthreads();
        if (step + 2 < 32) LOAD_PV(step + 2);
        CP_COMMIT();

        const uint32_t sA = sTiles + (step % 3) * PVSTAGE;
        const uint32_t sB = sA + TB64;
        #pragma unroll
        for (int ks = 0; ks < 4; ks++) {
            uint32_t a4[2][4];
            ldsm4(a4[0], sA + aoff + ks * 32);
            ldsm4(a4[1], sA + aoff + 16 * PITCHB2 + ks * 32);
            #pragma unroll
            for (int nf = 0; nf < 2; nf++) {
                uint32_t b4[4];
                ldsm4(b4, sB + boff + (uint32_t)(nf * (16 * PITCHB2) + ks * 32));
                #pragma unroll
                for (int m = 0; m < 2; m++)
                    #pragma unroll
                    for (int n8 = 0; n8 < 2; n8++)
                        mma16816h(acc[m * 4 + nf * 2 + n8], a4[m], b4 + n8 * 2);
            }
        }
    }
    #undef LOAD_PV
    // epilogue
    #pragma unroll
    for (int m = 0; m < 2; m++) {
        int row = wq * 32 + m * 16 + (lane >> 2);
        float inv0 = 1.0f / rsum[row];
        float inv1 = 1.0f / rsum[row + 8];
        #pragma unroll
        for (int f4 = 0; f4 < 4; f4++) {
            float* c = acc[m * 4 + f4];
            int col = dc * 128 + nh * 32 + f4 * 8 + (lane & 3) * 2;
            float* o0 = out + ((size_t)b * SQn + qt * 128 + row) * Dh + col;
            *(float2*)o0 = make_float2(c[0] * inv0, c[1] * inv0);
            *(float2*)(o0 + 8 * Dh) = make_float2(c[2] * inv1, c[3] * inv1);
        }
    }
}

extern "C" void kernel_launch(void* const* d_in, const int* in_sizes, int n_in,
                              void* d_out, int out_size) {
    (void)in_sizes; (void)n_in; (void)out_size;
    const float* q = (const float*)d_in[0];
    const float* k = (const float*)d_in[1];
    const float* v = (const float*)d_in[2];
    float* out = (float*)d_out;

    cudaFuncSetAttribute(qk_kern, cudaFuncAttributeMaxDynamicSharedMemorySize, SMEM_QK);
    cudaFuncSetAttribute(pv_kern, cudaFuncAttributeMaxDynamicSharedMemorySize, SMEM_PV);

    dim3 pgrid(SKn / 32, Dh / 32, Bn);
    prep_all<<<pgrid, 256>>>(q, k, v);
    dim3 g1(16, 16, Bn);
    qk_kern<<<g1, THREADS, SMEM_QK>>>();
    sm_kern<<<256, 256>>>();
    dim3 g3(4, 16, Bn);
    pv_kern<<<g3, THREADS, SMEM_PV>>>(out);
}